// round 15
// baseline (speedup 1.0000x reference)
#include <cuda_runtime.h>
#include <math.h>

#define Tn 1024
#define Hn 1024
#define En 64
#define In 512
#define TWO_I 1024
#define Gn 8
#define EPG 8
#define TOPKG 4
#define TOPK 8
#define NV 65                 // 64 routed + 1 shared (virtual expert 64)

#define BM 64
#define BK 32
// A and B fed raw fp32 -> tf32 truncation; product bias ~6.77e-4, corrected.
#define CF1 1.000677f
#define CF2 1.000677f

// ---------------- device scratch ----------------
__device__ int   g_counts[NV];
__device__ int   g_offsets[NV];
__device__ int   g_tokens[NV * Tn];
__device__ float g_wslot[NV * Tn];
__device__ float g_sc[Tn * En];
__device__ float g_ch[Tn * En];
__device__ float g_act[(size_t)(Tn * TOPK + Tn) * In];

// ---------------- helpers ----------------
__device__ __forceinline__ void mma_tf32(float* d, unsigned a0, unsigned a1,
                                         unsigned a2, unsigned a3,
                                         unsigned b0, unsigned b1) {
    asm volatile(
        "mma.sync.aligned.m16n8k8.row.col.f32.tf32.tf32.f32 "
        "{%0,%1,%2,%3}, {%4,%5,%6,%7}, {%8,%9}, {%0,%1,%2,%3};"
        : "+f"(d[0]), "+f"(d[1]), "+f"(d[2]), "+f"(d[3])
        : "r"(a0), "r"(a1), "r"(a2), "r"(a3), "r"(b0), "r"(b1));
}

__device__ __forceinline__ void cpa16(void* dst, const void* src) {
    unsigned d = (unsigned)__cvta_generic_to_shared(dst);
    asm volatile("cp.async.cg.shared.global [%0], [%1], 16;" :: "r"(d), "l"(src));
}
__device__ __forceinline__ void cpa_commit() { asm volatile("cp.async.commit_group;"); }
__device__ __forceinline__ void cpa_wait1()  { asm volatile("cp.async.wait_group 1;"); }
__device__ __forceinline__ void cpa_wait0()  { asm volatile("cp.async.wait_group 0;"); }

__device__ __forceinline__ void red_add_v2(float* p, float a, float b) {
    asm volatile("red.global.add.v2.f32 [%0], {%1, %2};"
                 :: "l"(p), "f"(a), "f"(b) : "memory");
}

#define AS_P 36    // mod32==4: A frag conflict-free
#define BG1  72    // mod32==8: gemm1 B frag conflict-free
#define BS2  136   // mod32==8: gemm2 B frag conflict-free

#define G1_STF (BM * AS_P + 2 * BK * BG1)   // 6912 floats / stage
#define G2_STF (BM * AS_P + BK * BS2)       // 6656 floats / stage

// ---------------- kernel 1a: routing logits (+ init) ----------------
__global__ __launch_bounds__(256) void k_logits(const float* __restrict__ x,
                                                const float* __restrict__ gw,
                                                const float* __restrict__ eb) {
    if (blockIdx.x == 0) {
        if (threadIdx.x < En) g_counts[threadIdx.x] = 0;
        if (threadIdx.x == En) g_counts[En] = Tn;
    }
    __shared__ float4 sx[8][256];
    const int t0 = blockIdx.x * 8;
    const int tid = threadIdx.x;

    #pragma unroll
    for (int l = 0; l < 8; l++) {
        int idx = tid + l * 256;
        int tok = idx >> 8, c = idx & 255;
        sx[tok][c] = ((const float4*)(x + (size_t)(t0 + tok) * Hn))[c];
    }
    __syncthreads();

    const int e = tid >> 2, p = tid & 3;
    const float4* gr = (const float4*)(gw + (size_t)e * Hn);
    float acc[8];
    #pragma unroll
    for (int tok = 0; tok < 8; tok++) acc[tok] = 0.f;

    #pragma unroll 4
    for (int k = 0; k < 64; k++) {
        float4 g = gr[p + 4 * k];
        #pragma unroll
        for (int tok = 0; tok < 8; tok++) {
            float4 xv = sx[tok][p + 4 * k];
            acc[tok] += g.x * xv.x + g.y * xv.y + g.z * xv.z + g.w * xv.w;
        }
    }
    #pragma unroll
    for (int tok = 0; tok < 8; tok++) {
        acc[tok] += __shfl_xor_sync(0xffffffffu, acc[tok], 1);
        acc[tok] += __shfl_xor_sync(0xffffffffu, acc[tok], 2);
    }
    if (p == 0) {
        float b = eb[e];
        #pragma unroll
        for (int tok = 0; tok < 8; tok++) {
            float sc = 1.f / (1.f + expf(-acc[tok]));
            g_sc[(t0 + tok) * En + e] = sc;
            g_ch[(t0 + tok) * En + e] = sc + b;
        }
    }
}

// ---------------- kernel 1b: grouped top-k selection ----------------
__global__ __launch_bounds__(256) void k_topk() {
    __shared__ float s_sc[8][En];
    __shared__ float s_ch[8][En];
    const int w = threadIdx.x >> 5, lane = threadIdx.x & 31;
    const int t = blockIdx.x * 8 + w;

    s_sc[w][lane]      = g_sc[t * En + lane];
    s_sc[w][lane + 32] = g_sc[t * En + lane + 32];
    s_ch[w][lane]      = g_ch[t * En + lane];
    s_ch[w][lane + 32] = g_ch[t * En + lane + 32];
    __syncwarp();

    if (lane == 0) {
        g_tokens[En * Tn + t] = t;
        g_wslot[En * Tn + t] = CF2;
        float gs[Gn];
        #pragma unroll
        for (int g = 0; g < Gn; g++) {
            float m1 = -1e38f, m2 = -1e38f;
            #pragma unroll
            for (int j = 0; j < EPG; j++) {
                float v = s_ch[w][g * EPG + j];
                if (v > m1) { m2 = m1; m1 = v; }
                else if (v > m2) { m2 = v; }
            }
            gs[g] = m1 + m2;
        }
        unsigned gsel = 0;
        #pragma unroll
        for (int it = 0; it < TOPKG; it++) {
            float best = -1e38f; int bi = 0;
            #pragma unroll
            for (int g = 0; g < Gn; g++)
                if (!((gsel >> g) & 1u) && gs[g] > best) { best = gs[g]; bi = g; }
            gsel |= 1u << bi;
        }
        unsigned long long taken = 0ull;
        int eidx[TOPK]; float ws[TOPK]; float wsum = 0.f;
        #pragma unroll
        for (int it = 0; it < TOPK; it++) {
            float best = -1e38f; int bi = 0;
            for (int ee = 0; ee < En; ee++) {
                if (((gsel >> (ee >> 3)) & 1u) && !((taken >> ee) & 1ull)) {
                    float v = s_ch[w][ee];
                    if (v > best) { best = v; bi = ee; }
                }
            }
            taken |= 1ull << bi;
            eidx[it] = bi; ws[it] = s_sc[w][bi]; wsum += s_sc[w][bi];
        }
        float scale = CF2 / wsum;
        #pragma unroll
        for (int k = 0; k < TOPK; k++) {
            int ee = eidx[k];
            int pos = atomicAdd(&g_counts[ee], 1);
            g_tokens[ee * Tn + pos] = t;
            g_wslot[ee * Tn + pos] = ws[k] * scale;
        }
    }
}

// ---------------- kernel 2: offsets ----------------
__global__ void k_scan() {
    __shared__ int s[NV];
    int tid = threadIdx.x;
    if (tid < NV) s[tid] = g_counts[tid];
    __syncthreads();
    if (tid == 0) {
        int off = 0;
        for (int e = 0; e < NV; e++) { g_offsets[e] = off; off += s[e]; }
    }
}

// ---------------- kernel 3: gate_up GEMM + SiLU*up ----------------
// 3-stage cp.async ring, depth-2 prefetch. Block 64M x (64g + 64u),
// 128 threads, 4 warps n-split, warp 64M x 16N dual. 2 CTAs/SM.
__global__ __launch_bounds__(128, 2) void k_gemm1(const float* __restrict__ x,
                                                  const float* __restrict__ wgu,
                                                  const float* __restrict__ shgu) {
    const int e = blockIdx.y;
    const int n_e = g_counts[e];
    const int nb = blockIdx.x & 7;
    const int mt = blockIdx.x >> 3;
    const int row0 = mt * BM;
    if (row0 >= n_e) return;
    const float* Bp = (e < En) ? (wgu + (size_t)e * Hn * TWO_I) : shgu;
    const int off_e = g_offsets[e];
    const int colg = nb * 64;

    extern __shared__ float smem[];  // 3 stages: [A 64x36 | Bg 32x72 | Bu 32x72]
    const int tid = threadIdx.x;

    const int ar = tid >> 3, ac = (tid & 7) * 4;
    const float* a_src[4];
    float* a_dst[4];   // stage-0 slots
    #pragma unroll
    for (int l = 0; l < 4; l++) {
        int r = l * 16 + ar;
        int ridx = row0 + r; if (ridx > n_e - 1) ridx = n_e - 1;
        a_src[l] = x + (size_t)g_tokens[e * Tn + ridx] * Hn + ac;
        a_dst[l] = smem + r * AS_P + ac;
    }
    const int brow = tid >> 4, bc4 = (tid & 15) * 4;
    const float* bgs = Bp + (size_t)brow * TWO_I + colg + bc4;
    const float* bus = bgs + In;
    float* bgd = smem + BM * AS_P + brow * BG1 + bc4;
    float* bud = bgd + BK * BG1;

    const int wn = tid >> 5, lane = tid & 31;
    const int qr = lane >> 2, qc = lane & 3;

    float accG[4][2][4], accU[4][2][4];
    #pragma unroll
    for (int m = 0; m < 4; m++)
        #pragma unroll
        for (int n = 0; n < 2; n++)
            #pragma unroll
            for (int j = 0; j < 4; j++) { accG[m][n][j] = 0.f; accU[m][n][j] = 0.f; }

    const int KT = Hn / BK;  // 32
    // prologue: stages 0 and 1
    #pragma unroll
    for (int s = 0; s < 2; s++) {
        const int so = s * G1_STF;
        const size_t ka = (size_t)s * BK;
        #pragma unroll
        for (int l = 0; l < 4; l++) cpa16(a_dst[l] + so, a_src[l] + ka);
        #pragma unroll
        for (int l = 0; l < 4; l++) {
            cpa16(bgd + so + l * 8 * BG1, bgs + ka * TWO_I + (size_t)l * 8 * TWO_I);
            cpa16(bud + so + l * 8 * BG1, bus + ka * TWO_I + (size_t)l * 8 * TWO_I);
        }
        cpa_commit();
    }

    for (int kt = 0; kt < KT; kt++) {
        if (kt == KT - 1) cpa_wait0(); else cpa_wait1();  // stage kt landed
        __syncthreads();   // globalize; all warps past compute(kt-1)
        if (kt + 2 < KT) {
            const int so = ((kt + 2) % 3) * G1_STF;
            const size_t ka = (size_t)(kt + 2) * BK;
            #pragma unroll
            for (int l = 0; l < 4; l++) cpa16(a_dst[l] + so, a_src[l] + ka);
            #pragma unroll
            for (int l = 0; l < 4; l++) {
                cpa16(bgd + so + l * 8 * BG1, bgs + ka * TWO_I + (size_t)l * 8 * TWO_I);
                cpa16(bud + so + l * 8 * BG1, bus + ka * TWO_I + (size_t)l * 8 * TWO_I);
            }
            cpa_commit();
        }

        const float* Ab  = smem + (kt % 3) * G1_STF;
        const float* Bgb = Ab + BM * AS_P;
        const float* Bub = Bgb + BK * BG1;
        #pragma unroll
        for (int ks = 0; ks < BK; ks += 8) {
            unsigned a[4][4];
            #pragma unroll
            for (int m = 0; m < 4; m++) {
                int r0 = m * 16 + qr;
                a[m][0] = __float_as_uint(Ab[r0 * AS_P + ks + qc]);
                a[m][1] = __float_as_uint(Ab[(r0 + 8) * AS_P + ks + qc]);
                a[m][2] = __float_as_uint(Ab[r0 * AS_P + ks + qc + 4]);
                a[m][3] = __float_as_uint(Ab[(r0 + 8) * AS_P + ks + qc + 4]);
            }
            #pragma unroll
            for (int n = 0; n < 2; n++) {
                int c = wn * 16 + n * 8 + qr;
                unsigned bg0 = __float_as_uint(Bgb[(ks + qc) * BG1 + c]);
                unsigned bg1 = __float_as_uint(Bgb[(ks + qc + 4) * BG1 + c]);
                #pragma unroll
                for (int m = 0; m < 4; m++)
                    mma_tf32(accG[m][n], a[m][0], a[m][1], a[m][2], a[m][3], bg0, bg1);
                unsigned bu0 = __float_as_uint(Bub[(ks + qc) * BG1 + c]);
                unsigned bu1 = __float_as_uint(Bub[(ks + qc + 4) * BG1 + c]);
                #pragma unroll
                for (int m = 0; m < 4; m++)
                    mma_tf32(accU[m][n], a[m][0], a[m][1], a[m][2], a[m][3], bu0, bu1);
            }
        }
    }

    // epilogue: bias-correct, silu(g)*u -> raw fp32
    #pragma unroll
    for (int m = 0; m < 4; m++) {
        #pragma unroll
        for (int n = 0; n < 2; n++) {
            #pragma unroll
            for (int half_ = 0; half_ < 2; half_++) {
                int r = m * 16 + qr + half_ * 8;
                int grow = row0 + r;
                if (grow < n_e) {
                    int c = colg + wn * 16 + n * 8 + qc * 2;
                    float gv0 = accG[m][n][half_ * 2 + 0] * CF1;
                    float uv0 = accU[m][n][half_ * 2 + 0] * CF1;
                    float gv1 = accG[m][n][half_ * 2 + 1] * CF1;
                    float uv1 = accU[m][n][half_ * 2 + 1] * CF1;
                    float2 o;
                    o.x = gv0 / (1.f + expf(-gv0)) * uv0;
                    o.y = gv1 / (1.f + expf(-gv1)) * uv1;
                    *(float2*)(g_act + (size_t)(off_e + grow) * In + c) = o;
                }
            }
        }
    }
}

// ---------------- kernel 4: down GEMM + fused weighted combine ----------------
// 3-stage ring, depth-2 prefetch. Block 64M x 128N, warp 64M x 32N. 2 CTAs/SM.
__global__ __launch_bounds__(128, 2) void k_gemm2(const float* __restrict__ wd,
                                                  const float* __restrict__ shd,
                                                  float* __restrict__ out) {
    const int e = blockIdx.y;
    const int n_e = g_counts[e];
    const int nb = blockIdx.x & 7;
    const int mt = blockIdx.x >> 3;
    const int row0 = mt * BM;
    if (row0 >= n_e) return;
    const float* Bp = (e < En) ? (wd + (size_t)e * In * Hn) : shd;
    const int off_e = g_offsets[e];
    const int colb = nb * 128;

    extern __shared__ float smem[];  // 3 stages: [A 64x36 | B 32x136]
    const int tid = threadIdx.x;

    const int ar = tid >> 3, ac = (tid & 7) * 4;
    const float* a_src[4];
    float* a_dst[4];
    #pragma unroll
    for (int l = 0; l < 4; l++) {
        int r = l * 16 + ar;
        int ridx = row0 + r; if (ridx > n_e - 1) ridx = n_e - 1;
        a_src[l] = g_act + (size_t)(off_e + ridx) * In + ac;
        a_dst[l] = smem + r * AS_P + ac;
    }
    const int brow = tid >> 5, bc4 = (tid & 31) * 4;
    const float* bss = Bp + (size_t)brow * Hn + colb + bc4;
    float* bsd = smem + BM * AS_P + brow * BS2 + bc4;

    const int wn = tid >> 5, lane = tid & 31;
    const int qr = lane >> 2, qc = lane & 3;

    float acc[4][4][4];
    #pragma unroll
    for (int m = 0; m < 4; m++)
        #pragma unroll
        for (int n = 0; n < 4; n++)
            #pragma unroll
            for (int j = 0; j < 4; j++) acc[m][n][j] = 0.f;

    const int KT = In / BK;  // 16
    #pragma unroll
    for (int s = 0; s < 2; s++) {
        const int so = s * G2_STF;
        const size_t ka = (size_t)s * BK;
        #pragma unroll
        for (int l = 0; l < 4; l++) cpa16(a_dst[l] + so, a_src[l] + ka);
        #pragma unroll
        for (int l = 0; l < 8; l++)
            cpa16(bsd + so + l * 4 * BS2, bss + ka * Hn + (size_t)l * 4 * Hn);
        cpa_commit();
    }

    for (int kt = 0; kt < KT; kt++) {
        if (kt == KT - 1) cpa_wait0(); else cpa_wait1();
        __syncthreads();
        if (kt + 2 < KT) {
            const int so = ((kt + 2) % 3) * G2_STF;
            const size_t ka = (size_t)(kt + 2) * BK;
            #pragma unroll
            for (int l = 0; l < 4; l++) cpa16(a_dst[l] + so, a_src[l] + ka);
            #pragma unroll
            for (int l = 0; l < 8; l++)
                cpa16(bsd + so + l * 4 * BS2, bss + ka * Hn + (size_t)l * 4 * Hn);
            cpa_commit();
        }

        const float* Ab = smem + (kt % 3) * G2_STF;
        const float* Bb = Ab + BM * AS_P;
        #pragma unroll
        for (int ks = 0; ks < BK; ks += 8) {
            unsigned a[4][4];
            #pragma unroll
            for (int m = 0; m < 4; m++) {
                int r0 = m * 16 + qr;
                a[m][0] = __float_as_uint(Ab[r0 * AS_P + ks + qc]);
                a[m][1] = __float_as_uint(Ab[(r0 + 8) * AS_P + ks + qc]);
                a[m][2] = __float_as_uint(Ab[r0 * AS_P + ks + qc + 4]);
                a[m][3] = __float_as_uint(Ab[(r0 + 8) * AS_P + ks + qc + 4]);
            }
            #pragma unroll
            for (int n = 0; n < 4; n++) {
                int c = wn * 32 + n * 8 + qr;
                unsigned b0 = __float_as_uint(Bb[(ks + qc) * BS2 + c]);
                unsigned b1 = __float_as_uint(Bb[(ks + qc + 4) * BS2 + c]);
                #pragma unroll
                for (int m = 0; m < 4; m++)
                    mma_tf32(acc[m][n], a[m][0], a[m][1], a[m][2], a[m][3], b0, b1);
            }
        }
    }

    // epilogue: weighted scatter-accumulate into out[token]
    #pragma unroll
    for (int m = 0; m < 4; m++) {
        #pragma unroll
        for (int half_ = 0; half_ < 2; half_++) {
            int r = m * 16 + qr + half_ * 8;
            int grow = row0 + r;
            if (grow < n_e) {
                int tok  = g_tokens[e * Tn + grow];
                float wv = g_wslot[e * Tn + grow];
                float* orow = out + (size_t)tok * Hn + colb + wn * 32 + qc * 2;
                #pragma unroll
                for (int n = 0; n < 4; n++) {
                    red_add_v2(orow + n * 8,
                               acc[m][n][half_ * 2 + 0] * wv,
                               acc[m][n][half_ * 2 + 1] * wv);
                }
            }
        }
    }
}

// ---------------- launch ----------------
extern "C" void kernel_launch(void* const* d_in, const int* in_sizes, int n_in,
                              void* d_out, int out_size) {
    const float* x    = (const float*)d_in[0];
    const float* gw   = (const float*)d_in[1];
    const float* eb   = (const float*)d_in[2];
    const float* wgu  = (const float*)d_in[3];
    const float* wd   = (const float*)d_in[4];
    const float* shgu = (const float*)d_in[5];
    const float* shd  = (const float*)d_in[6];
    float* out = (float*)d_out;

    const int smem1 = 3 * G1_STF * 4;   // 82944 B
    const int smem2 = 3 * G2_STF * 4;   // 79872 B
    cudaFuncSetAttribute(k_gemm1, cudaFuncAttributeMaxDynamicSharedMemorySize, smem1);
    cudaFuncSetAttribute(k_gemm2, cudaFuncAttributeMaxDynamicSharedMemorySize, smem2);

    cudaMemsetAsync(out, 0, (size_t)out_size * sizeof(float));
    k_logits<<<Tn / 8, 256>>>(x, gw, eb);
    k_topk<<<Tn / 8, 256>>>();
    k_scan<<<1, 128>>>();
    k_gemm1<<<dim3(16 * 8, NV), 128, smem1>>>(x, wgu, shgu);
    k_gemm2<<<dim3(16 * 8, NV), 128, smem2>>>(wd, shd, out);
}

// round 16
// speedup vs baseline: 1.1196x; 1.1196x over previous
#include <cuda_runtime.h>
#include <math.h>

#define Tn 1024
#define Hn 1024
#define En 64
#define In 512
#define TWO_I 1024
#define Gn 8
#define EPG 8
#define TOPKG 4
#define TOPK 8
#define NV 65                 // 64 routed + 1 shared (virtual expert 64)

#define BM 64
#define BK 32
// A and B fed raw fp32 -> tf32 truncation; product bias ~6.77e-4, corrected.
#define CF1 1.000677f
#define CF2 1.000677f

// ---------------- device scratch ----------------
__device__ int   g_counts[En];                     // routed experts only
__device__ int   g_tokens[En * Tn];
__device__ float g_wslot[En * Tn];
__device__ float g_act[(size_t)NV * Tn * In];      // slot = e*Tn + row (uncompacted)

// ---------------- helpers ----------------
__device__ __forceinline__ void mma_tf32(float* d, unsigned a0, unsigned a1,
                                         unsigned a2, unsigned a3,
                                         unsigned b0, unsigned b1) {
    asm volatile(
        "mma.sync.aligned.m16n8k8.row.col.f32.tf32.tf32.f32 "
        "{%0,%1,%2,%3}, {%4,%5,%6,%7}, {%8,%9}, {%0,%1,%2,%3};"
        : "+f"(d[0]), "+f"(d[1]), "+f"(d[2]), "+f"(d[3])
        : "r"(a0), "r"(a1), "r"(a2), "r"(a3), "r"(b0), "r"(b1));
}

__device__ __forceinline__ void cpa16(void* dst, const void* src) {
    unsigned d = (unsigned)__cvta_generic_to_shared(dst);
    asm volatile("cp.async.cg.shared.global [%0], [%1], 16;" :: "r"(d), "l"(src));
}
__device__ __forceinline__ void cpa_commit() { asm volatile("cp.async.commit_group;"); }
__device__ __forceinline__ void cpa_wait0()  { asm volatile("cp.async.wait_group 0;"); }

__device__ __forceinline__ void red_add_v2(float* p, float a, float b) {
    asm volatile("red.global.add.v2.f32 [%0], {%1, %2};"
                 :: "l"(p), "f"(a), "f"(b) : "memory");
}

#define AS_P 36    // mod32==4: A frag conflict-free
#define BGP  136   // mod32==8: B frag conflict-free
#define BSP2 264   // mod32==8

// ---------------- kernel 1: fused routing (logits + grouped top-k) ----------------
// 8 tokens/block, 256 threads = 64 experts x 4 quarters. Scores stay in smem;
// selection done by 8 threads (one per token) with exact reference semantics.
__global__ __launch_bounds__(256) void k_route(const float* __restrict__ x,
                                               const float* __restrict__ gw,
                                               const float* __restrict__ eb) {
    __shared__ float4 sx[8][256];
    __shared__ float s_sc[8][En];
    __shared__ float s_ch[8][En];
    const int t0 = blockIdx.x * 8;
    const int tid = threadIdx.x;

    #pragma unroll
    for (int l = 0; l < 8; l++) {
        int idx = tid + l * 256;
        int tok = idx >> 8, c = idx & 255;
        sx[tok][c] = ((const float4*)(x + (size_t)(t0 + tok) * Hn))[c];
    }
    __syncthreads();

    const int e = tid >> 2, p = tid & 3;
    const float4* gr = (const float4*)(gw + (size_t)e * Hn);
    float acc[8];
    #pragma unroll
    for (int tok = 0; tok < 8; tok++) acc[tok] = 0.f;

    #pragma unroll 4
    for (int k = 0; k < 64; k++) {
        float4 g = gr[p + 4 * k];
        #pragma unroll
        for (int tok = 0; tok < 8; tok++) {
            float4 xv = sx[tok][p + 4 * k];
            acc[tok] += g.x * xv.x + g.y * xv.y + g.z * xv.z + g.w * xv.w;
        }
    }
    #pragma unroll
    for (int tok = 0; tok < 8; tok++) {
        acc[tok] += __shfl_xor_sync(0xffffffffu, acc[tok], 1);
        acc[tok] += __shfl_xor_sync(0xffffffffu, acc[tok], 2);
    }
    if (p == 0) {
        float b = eb[e];
        #pragma unroll
        for (int tok = 0; tok < 8; tok++) {
            float sc = 1.f / (1.f + expf(-acc[tok]));
            s_sc[tok][e] = sc;
            s_ch[tok][e] = sc + b;
        }
    }
    __syncthreads();

    if (tid < 8) {
        const int w = tid;
        const int t = t0 + w;
        float gs[Gn];
        #pragma unroll
        for (int g = 0; g < Gn; g++) {
            float m1 = -1e38f, m2 = -1e38f;
            #pragma unroll
            for (int j = 0; j < EPG; j++) {
                float v = s_ch[w][g * EPG + j];
                if (v > m1) { m2 = m1; m1 = v; }
                else if (v > m2) { m2 = v; }
            }
            gs[g] = m1 + m2;
        }
        unsigned gsel = 0;
        #pragma unroll
        for (int it = 0; it < TOPKG; it++) {
            float best = -1e38f; int bi = 0;
            #pragma unroll
            for (int g = 0; g < Gn; g++)
                if (!((gsel >> g) & 1u) && gs[g] > best) { best = gs[g]; bi = g; }
            gsel |= 1u << bi;
        }
        unsigned long long taken = 0ull;
        int eidx[TOPK]; float ws[TOPK]; float wsum = 0.f;
        #pragma unroll
        for (int it = 0; it < TOPK; it++) {
            float best = -1e38f; int bi = 0;
            for (int ee = 0; ee < En; ee++) {
                if (((gsel >> (ee >> 3)) & 1u) && !((taken >> ee) & 1ull)) {
                    float v = s_ch[w][ee];
                    if (v > best) { best = v; bi = ee; }
                }
            }
            taken |= 1ull << bi;
            eidx[it] = bi; ws[it] = s_sc[w][bi]; wsum += s_sc[w][bi];
        }
        float scale = CF2 / wsum;   // renormalize, RSF=1, fold gemm2 bias correction
        #pragma unroll
        for (int k = 0; k < TOPK; k++) {
            int ee = eidx[k];
            int pos = atomicAdd(&g_counts[ee], 1);
            g_tokens[ee * Tn + pos] = t;
            g_wslot[ee * Tn + pos] = ws[k] * scale;
        }
    }
}

// ---------------- kernel 3: gate_up GEMM + SiLU*up (tf32 raw-bit, R12 shape) ----
// 128 threads, 4 warps in n. Block 64M x (128 gate + 128 up). Warp 64M x 32N dual.
// Loop: wait0 -> sync -> prefetch(kt+1) -> compute(kt).
__global__ __launch_bounds__(128, 2) void k_gemm1(const float* __restrict__ x,
                                                  const float* __restrict__ wgu,
                                                  const float* __restrict__ shgu) {
    const int e = blockIdx.y;
    const int n_e = (e < En) ? g_counts[e] : Tn;
    const int nb = blockIdx.x & 3;
    const int mt = blockIdx.x >> 2;
    const int row0 = mt * BM;
    if (row0 >= n_e) return;
    const float* Bp = (e < En) ? (wgu + (size_t)e * Hn * TWO_I) : shgu;
    const int colg = nb * 128;

    extern __shared__ float smem[];
    float* As = smem;                    // [2][64][AS_P]
    float* Bg = smem + 2 * BM * AS_P;    // [2][32][BGP]
    float* Bu = Bg + 2 * BK * BGP;       // [2][32][BGP]

    const int tid = threadIdx.x;

    const int ar = tid >> 3, ac = (tid & 7) * 4;
    const float* a_src[4];
    float* a_dst[4];
    #pragma unroll
    for (int l = 0; l < 4; l++) {
        int r = l * 16 + ar;
        int ridx = row0 + r; if (ridx > n_e - 1) ridx = n_e - 1;
        int tok = (e < En) ? g_tokens[e * Tn + ridx] : ridx;
        a_src[l] = x + (size_t)tok * Hn + ac;
        a_dst[l] = As + r * AS_P + ac;
    }
    const int br = tid >> 5, bc = (tid & 31) * 4;
    const float* bgs = Bp + (size_t)br * TWO_I + colg + bc;
    const float* bus = bgs + In;
    float* bgd = Bg + br * BGP + bc;
    float* bud = Bu + br * BGP + bc;

    const int wn = tid >> 5, lane = tid & 31;
    const int qr = lane >> 2, qc = lane & 3;
    const int abuf = BM * AS_P, bbuf = BK * BGP;

    float accG[4][4][4], accU[4][4][4];
    #pragma unroll
    for (int m = 0; m < 4; m++)
        #pragma unroll
        for (int n = 0; n < 4; n++)
            #pragma unroll
            for (int j = 0; j < 4; j++) { accG[m][n][j] = 0.f; accU[m][n][j] = 0.f; }

    // prologue: stage 0 -> buf 0
    #pragma unroll
    for (int l = 0; l < 4; l++) cpa16(a_dst[l], a_src[l]);
    #pragma unroll
    for (int l = 0; l < 8; l++) {
        cpa16(bgd + l * 4 * BGP, bgs + (size_t)l * 4 * TWO_I);
        cpa16(bud + l * 4 * BGP, bus + (size_t)l * 4 * TWO_I);
    }
    cpa_commit();

    const int KT = Hn / BK;  // 32
    for (int kt = 0; kt < KT; kt++) {
        const int buf = kt & 1;
        cpa_wait0();       // own stage-kt copies retired
        __syncthreads();   // globalize stage-kt; all warps past compute(kt-1)
        if (kt + 1 < KT) {
            const int aoff = (buf ^ 1) ? abuf : 0;
            const int boff = (buf ^ 1) ? bbuf : 0;
            const size_t ka = (size_t)(kt + 1) * BK;
            #pragma unroll
            for (int l = 0; l < 4; l++) cpa16(a_dst[l] + aoff, a_src[l] + ka);
            #pragma unroll
            for (int l = 0; l < 8; l++) {
                cpa16(bgd + boff + l * 4 * BGP, bgs + ka * TWO_I + (size_t)l * 4 * TWO_I);
                cpa16(bud + boff + l * 4 * BGP, bus + ka * TWO_I + (size_t)l * 4 * TWO_I);
            }
            cpa_commit();
        }

        const float* Ab = As + buf * abuf;
        const float* Bgb = Bg + buf * bbuf;
        const float* Bub = Bu + buf * bbuf;
        #pragma unroll
        for (int ks = 0; ks < BK; ks += 8) {
            unsigned a[4][4];
            #pragma unroll
            for (int m = 0; m < 4; m++) {
                int r0 = m * 16 + qr;
                a[m][0] = __float_as_uint(Ab[r0 * AS_P + ks + qc]);
                a[m][1] = __float_as_uint(Ab[(r0 + 8) * AS_P + ks + qc]);
                a[m][2] = __float_as_uint(Ab[r0 * AS_P + ks + qc + 4]);
                a[m][3] = __float_as_uint(Ab[(r0 + 8) * AS_P + ks + qc + 4]);
            }
            #pragma unroll
            for (int n = 0; n < 4; n++) {
                int c = wn * 32 + n * 8 + qr;
                unsigned bg0 = __float_as_uint(Bgb[(ks + qc) * BGP + c]);
                unsigned bg1 = __float_as_uint(Bgb[(ks + qc + 4) * BGP + c]);
                #pragma unroll
                for (int m = 0; m < 4; m++)
                    mma_tf32(accG[m][n], a[m][0], a[m][1], a[m][2], a[m][3], bg0, bg1);
                unsigned bu0 = __float_as_uint(Bub[(ks + qc) * BGP + c]);
                unsigned bu1 = __float_as_uint(Bub[(ks + qc + 4) * BGP + c]);
                #pragma unroll
                for (int m = 0; m < 4; m++)
                    mma_tf32(accU[m][n], a[m][0], a[m][1], a[m][2], a[m][3], bu0, bu1);
            }
        }
    }

    // epilogue: bias-correct, silu(g)*u -> raw fp32 (slot = e*Tn + row)
    float* arow_base = g_act + (size_t)e * Tn * In;
    #pragma unroll
    for (int m = 0; m < 4; m++) {
        #pragma unroll
        for (int n = 0; n < 4; n++) {
            #pragma unroll
            for (int half_ = 0; half_ < 2; half_++) {
                int r = m * 16 + qr + half_ * 8;
                int grow = row0 + r;
                if (grow < n_e) {
                    int c = colg + wn * 32 + n * 8 + qc * 2;
                    float gv0 = accG[m][n][half_ * 2 + 0] * CF1;
                    float uv0 = accU[m][n][half_ * 2 + 0] * CF1;
                    float gv1 = accG[m][n][half_ * 2 + 1] * CF1;
                    float uv1 = accU[m][n][half_ * 2 + 1] * CF1;
                    float2 o;
                    o.x = gv0 / (1.f + expf(-gv0)) * uv0;
                    o.y = gv1 / (1.f + expf(-gv1)) * uv1;
                    *(float2*)(arow_base + (size_t)grow * In + c) = o;
                }
            }
        }
    }
}

// ---------------- kernel 4: down GEMM (tf32 raw-bit) + fused weighted combine ----
// R12 shape: 128 threads, block 64M x 256N, warp 64M x 64N. Epilogue applies the
// routing weight and red.global.add.v2.f32 into out[token] (L2-resident 4MB).
__global__ __launch_bounds__(128, 2) void k_gemm2(const float* __restrict__ wd,
                                                  const float* __restrict__ shd,
                                                  float* __restrict__ out) {
    const int e = blockIdx.y;
    const int n_e = (e < En) ? g_counts[e] : Tn;
    const int nb = blockIdx.x & 3;
    const int mt = blockIdx.x >> 2;
    const int row0 = mt * BM;
    if (row0 >= n_e) return;
    const float* Bp = (e < En) ? (wd + (size_t)e * In * Hn) : shd;
    const int colb = nb * 256;

    extern __shared__ float smem[];
    float* As = smem;                    // [2][64][AS_P]
    float* Bs = smem + 2 * BM * AS_P;    // [2][32][BSP2]

    const int tid = threadIdx.x;
    const float* arow_base = g_act + (size_t)e * Tn * In;

    const int ar = tid >> 3, ac = (tid & 7) * 4;
    const float* a_src[4];
    float* a_dst[4];
    #pragma unroll
    for (int l = 0; l < 4; l++) {
        int r = l * 16 + ar;
        int ridx = row0 + r; if (ridx > n_e - 1) ridx = n_e - 1;
        a_src[l] = arow_base + (size_t)ridx * In + ac;
        a_dst[l] = As + r * AS_P + ac;
    }
    const int br = tid >> 6, bc = (tid & 63) * 4;
    const float* bss = Bp + (size_t)br * Hn + colb + bc;
    float* bsd = Bs + br * BSP2 + bc;

    const int wn = tid >> 5, lane = tid & 31;
    const int qr = lane >> 2, qc = lane & 3;
    const int abuf = BM * AS_P, bbuf = BK * BSP2;

    float acc[4][8][4];
    #pragma unroll
    for (int m = 0; m < 4; m++)
        #pragma unroll
        for (int n = 0; n < 8; n++)
            #pragma unroll
            for (int j = 0; j < 4; j++) acc[m][n][j] = 0.f;

    #pragma unroll
    for (int l = 0; l < 4; l++) cpa16(a_dst[l], a_src[l]);
    #pragma unroll
    for (int l = 0; l < 16; l++)
        cpa16(bsd + l * 2 * BSP2, bss + (size_t)l * 2 * Hn);
    cpa_commit();

    const int KT = In / BK;  // 16
    for (int kt = 0; kt < KT; kt++) {
        const int buf = kt & 1;
        cpa_wait0();
        __syncthreads();
        if (kt + 1 < KT) {
            const int aoff = (buf ^ 1) ? abuf : 0;
            const int boff = (buf ^ 1) ? bbuf : 0;
            const size_t ka = (size_t)(kt + 1) * BK;
            #pragma unroll
            for (int l = 0; l < 4; l++) cpa16(a_dst[l] + aoff, a_src[l] + ka);
            #pragma unroll
            for (int l = 0; l < 16; l++)
                cpa16(bsd + boff + l * 2 * BSP2, bss + ka * Hn + (size_t)l * 2 * Hn);
            cpa_commit();
        }

        const float* Ab = As + buf * abuf;
        const float* Bb = Bs + buf * bbuf;
        #pragma unroll
        for (int ks = 0; ks < BK; ks += 8) {
            unsigned a[4][4];
            #pragma unroll
            for (int m = 0; m < 4; m++) {
                int r0 = m * 16 + qr;
                a[m][0] = __float_as_uint(Ab[r0 * AS_P + ks + qc]);
                a[m][1] = __float_as_uint(Ab[(r0 + 8) * AS_P + ks + qc]);
                a[m][2] = __float_as_uint(Ab[r0 * AS_P + ks + qc + 4]);
                a[m][3] = __float_as_uint(Ab[(r0 + 8) * AS_P + ks + qc + 4]);
            }
            #pragma unroll
            for (int n = 0; n < 8; n++) {
                int c = wn * 64 + n * 8 + qr;
                unsigned b0 = __float_as_uint(Bb[(ks + qc) * BSP2 + c]);
                unsigned b1 = __float_as_uint(Bb[(ks + qc + 4) * BSP2 + c]);
                #pragma unroll
                for (int m = 0; m < 4; m++)
                    mma_tf32(acc[m][n], a[m][0], a[m][1], a[m][2], a[m][3], b0, b1);
            }
        }
    }

    // epilogue: weighted scatter-accumulate into out[token]
    #pragma unroll
    for (int m = 0; m < 4; m++) {
        #pragma unroll
        for (int half_ = 0; half_ < 2; half_++) {
            int r = m * 16 + qr + half_ * 8;
            int grow = row0 + r;
            if (grow < n_e) {
                int tok;
                float wv;
                if (e < En) {
                    tok = g_tokens[e * Tn + grow];
                    wv  = g_wslot[e * Tn + grow];
                } else {
                    tok = grow;
                    wv  = CF2;
                }
                float* orow = out + (size_t)tok * Hn + colb + wn * 64 + qc * 2;
                #pragma unroll
                for (int n = 0; n < 8; n++) {
                    red_add_v2(orow + n * 8,
                               acc[m][n][half_ * 2 + 0] * wv,
                               acc[m][n][half_ * 2 + 1] * wv);
                }
            }
        }
    }
}

// ---------------- launch ----------------
extern "C" void kernel_launch(void* const* d_in, const int* in_sizes, int n_in,
                              void* d_out, int out_size) {
    const float* x    = (const float*)d_in[0];
    const float* gw   = (const float*)d_in[1];
    const float* eb   = (const float*)d_in[2];
    const float* wgu  = (const float*)d_in[3];
    const float* wd   = (const float*)d_in[4];
    const float* shgu = (const float*)d_in[5];
    const float* shd  = (const float*)d_in[6];
    float* out = (float*)d_out;

    const int smem1 = (2 * BM * AS_P + 4 * BK * BGP) * 4;   // 88064 B
    const int smem2 = (2 * BM * AS_P + 2 * BK * BSP2) * 4;  // 86016 B
    cudaFuncSetAttribute(k_gemm1, cudaFuncAttributeMaxDynamicSharedMemorySize, smem1);
    cudaFuncSetAttribute(k_gemm2, cudaFuncAttributeMaxDynamicSharedMemorySize, smem2);

    void* counts_ptr = nullptr;
    cudaGetSymbolAddress(&counts_ptr, g_counts);

    cudaMemsetAsync(out, 0, (size_t)out_size * sizeof(float));
    cudaMemsetAsync(counts_ptr, 0, En * sizeof(int));
    k_route<<<Tn / 8, 256>>>(x, gw, eb);
    k_gemm1<<<dim3(16 * 4, NV), 128, smem1>>>(x, wgu, shgu);
    k_gemm2<<<dim3(16 * 4, NV), 128, smem2>>>(wd, shd, out);
}

// round 17
// speedup vs baseline: 1.1283x; 1.0078x over previous
#include <cuda_runtime.h>
#include <math.h>

#define Tn 1024
#define Hn 1024
#define En 64
#define In 512
#define TWO_I 1024
#define Gn 8
#define EPG 8
#define TOPKG 4
#define TOPK 8
#define NV 65                 // 64 routed + 1 shared (virtual expert 64)

#define BM 64
#define BK 32
// A and B fed raw fp32 -> tf32 truncation; product bias ~6.77e-4, corrected.
#define CF1 1.000677f
#define CF2 1.000677f

// ---------------- device scratch ----------------
__device__ int   g_counts[En];                     // routed experts only
__device__ int   g_tokens[En * Tn];
__device__ float g_wslot[En * Tn];
__device__ float g_act[(size_t)NV * Tn * In];      // slot = e*Tn + row (uncompacted)

// ---------------- helpers ----------------
__device__ __forceinline__ void mma_tf32(float* d, unsigned a0, unsigned a1,
                                         unsigned a2, unsigned a3,
                                         unsigned b0, unsigned b1) {
    asm volatile(
        "mma.sync.aligned.m16n8k8.row.col.f32.tf32.tf32.f32 "
        "{%0,%1,%2,%3}, {%4,%5,%6,%7}, {%8,%9}, {%0,%1,%2,%3};"
        : "+f"(d[0]), "+f"(d[1]), "+f"(d[2]), "+f"(d[3])
        : "r"(a0), "r"(a1), "r"(a2), "r"(a3), "r"(b0), "r"(b1));
}

__device__ __forceinline__ void cpa16(void* dst, const void* src) {
    unsigned d = (unsigned)__cvta_generic_to_shared(dst);
    asm volatile("cp.async.cg.shared.global [%0], [%1], 16;" :: "r"(d), "l"(src));
}
__device__ __forceinline__ void cpa_commit() { asm volatile("cp.async.commit_group;"); }
__device__ __forceinline__ void cpa_wait0()  { asm volatile("cp.async.wait_group 0;"); }

__device__ __forceinline__ void red_add_v2(float* p, float a, float b) {
    asm volatile("red.global.add.v2.f32 [%0], {%1, %2};"
                 :: "l"(p), "f"(a), "f"(b) : "memory");
}

#define AS_P 36    // mod32==4: A frag conflict-free
#define BGP  136   // mod32==8: B frag conflict-free
#define BSP2 264   // mod32==8

// ---------------- kernel 1: fused routing (logits + warp-parallel top-k) --------
// 4 tokens/block, 256 blocks. Logits: 256 threads = 64 experts x 4 quarters.
// Selection: warp w (0-3) handles token w via warp-argmax reductions with exact
// reference tie semantics (strict '>', ties -> lowest index).
__global__ __launch_bounds__(256) void k_route(const float* __restrict__ x,
                                               const float* __restrict__ gw,
                                               const float* __restrict__ eb) {
    __shared__ float4 sx[4][256];        // 16 KB
    __shared__ float s_sc[4][En];
    __shared__ float s_ch[4][En];
    __shared__ float s_gs[4][Gn];
    __shared__ int   s_sel[4][TOPK];
    __shared__ float s_wv[4][TOPK];
    const int t0 = blockIdx.x * 4;
    const int tid = threadIdx.x;

    #pragma unroll
    for (int l = 0; l < 4; l++) {
        int idx = tid + l * 256;
        int tok = idx >> 8, c = idx & 255;
        sx[tok][c] = ((const float4*)(x + (size_t)(t0 + tok) * Hn))[c];
    }
    __syncthreads();

    {   // logits for 4 tokens
        const int e = tid >> 2, p = tid & 3;
        const float4* gr = (const float4*)(gw + (size_t)e * Hn);
        float acc[4] = {0.f, 0.f, 0.f, 0.f};
        #pragma unroll 8
        for (int k = 0; k < 64; k++) {
            float4 g = gr[p + 4 * k];
            #pragma unroll
            for (int tok = 0; tok < 4; tok++) {
                float4 xv = sx[tok][p + 4 * k];
                acc[tok] += g.x * xv.x + g.y * xv.y + g.z * xv.z + g.w * xv.w;
            }
        }
        #pragma unroll
        for (int tok = 0; tok < 4; tok++) {
            acc[tok] += __shfl_xor_sync(0xffffffffu, acc[tok], 1);
            acc[tok] += __shfl_xor_sync(0xffffffffu, acc[tok], 2);
        }
        if (p == 0) {
            float b = eb[e];
            #pragma unroll
            for (int tok = 0; tok < 4; tok++) {
                float sc = 1.f / (1.f + expf(-acc[tok]));
                s_sc[tok][e] = sc;
                s_ch[tok][e] = sc + b;
            }
        }
    }
    __syncthreads();

    const int w = tid >> 5, lane = tid & 31;
    if (w < 4) {
        const int t = t0 + w;
        // per-lane candidates: experts lane and lane+32
        float v0 = s_ch[w][lane],  v1 = s_ch[w][lane + 32];
        float c0 = s_sc[w][lane],  c1 = s_sc[w][lane + 32];

        // group scores: lanes 0-7 compute top-2 sum of group `lane`
        if (lane < Gn) {
            float m1 = -1e38f, m2 = -1e38f;
            #pragma unroll
            for (int j = 0; j < EPG; j++) {
                float v = s_ch[w][lane * EPG + j];
                if (v > m1) { m2 = m1; m1 = v; }
                else if (v > m2) { m2 = v; }
            }
            s_gs[w][lane] = m1 + m2;
        }
        __syncwarp();
        unsigned gsel = 0;
        if (lane == 0) {
            #pragma unroll
            for (int it = 0; it < TOPKG; it++) {
                float best = -1e38f; int bi = 0;
                #pragma unroll
                for (int g = 0; g < Gn; g++)
                    if (!((gsel >> g) & 1u) && s_gs[w][g] > best) { best = s_gs[w][g]; bi = g; }
                gsel |= 1u << bi;
            }
        }
        gsel = __shfl_sync(0xffffffffu, gsel, 0);

        const bool allowed0 = (gsel >> (lane >> 3)) & 1u;
        const bool allowed1 = (gsel >> ((lane + 32) >> 3)) & 1u;
        bool taken0 = false, taken1 = false;
        float wsum = 0.f;

        #pragma unroll
        for (int it = 0; it < TOPK; it++) {
            float bv = -1e38f; int bi = 64;
            if (allowed0 && !taken0) { bv = v0; bi = lane; }
            if (allowed1 && !taken1 && v1 > bv) { bv = v1; bi = lane + 32; }
            #pragma unroll
            for (int off = 16; off > 0; off >>= 1) {
                float ov = __shfl_xor_sync(0xffffffffu, bv, off);
                int   oi = __shfl_xor_sync(0xffffffffu, bi, off);
                if (ov > bv || (ov == bv && oi < bi)) { bv = ov; bi = oi; }
            }
            if (bi == lane)      taken0 = true;
            if (bi == lane + 32) taken1 = true;
            float sw = (bi < 32) ? __shfl_sync(0xffffffffu, c0, bi)
                                 : __shfl_sync(0xffffffffu, c1, bi - 32);
            if (lane == 0) { s_sel[w][it] = bi; s_wv[w][it] = sw; }
            wsum += sw;
        }
        __syncwarp();

        const float scale = CF2 / wsum;
        if (lane < TOPK) {
            int ee = s_sel[w][lane];
            int pos = atomicAdd(&g_counts[ee], 1);
            g_tokens[ee * Tn + pos] = t;
            g_wslot[ee * Tn + pos] = s_wv[w][lane] * scale;
        }
    }
}

// ---------------- kernel 3: gate_up GEMM + SiLU*up (tf32 raw-bit, R12 shape) ----
// 128 threads, 4 warps in n. Block 64M x (128 gate + 128 up). Warp 64M x 32N dual.
// Loop: wait0 -> sync -> prefetch(kt+1) -> compute(kt).
__global__ __launch_bounds__(128, 2) void k_gemm1(const float* __restrict__ x,
                                                  const float* __restrict__ wgu,
                                                  const float* __restrict__ shgu) {
    const int e = blockIdx.y;
    const int n_e = (e < En) ? g_counts[e] : Tn;
    const int nb = blockIdx.x & 3;
    const int mt = blockIdx.x >> 2;
    const int row0 = mt * BM;
    if (row0 >= n_e) return;
    const float* Bp = (e < En) ? (wgu + (size_t)e * Hn * TWO_I) : shgu;
    const int colg = nb * 128;

    extern __shared__ float smem[];
    float* As = smem;                    // [2][64][AS_P]
    float* Bg = smem + 2 * BM * AS_P;    // [2][32][BGP]
    float* Bu = Bg + 2 * BK * BGP;       // [2][32][BGP]

    const int tid = threadIdx.x;

    const int ar = tid >> 3, ac = (tid & 7) * 4;
    const float* a_src[4];
    float* a_dst[4];
    #pragma unroll
    for (int l = 0; l < 4; l++) {
        int r = l * 16 + ar;
        int ridx = row0 + r; if (ridx > n_e - 1) ridx = n_e - 1;
        int tok = (e < En) ? g_tokens[e * Tn + ridx] : ridx;
        a_src[l] = x + (size_t)tok * Hn + ac;
        a_dst[l] = As + r * AS_P + ac;
    }
    const int br = tid >> 5, bc = (tid & 31) * 4;
    const float* bgs = Bp + (size_t)br * TWO_I + colg + bc;
    const float* bus = bgs + In;
    float* bgd = Bg + br * BGP + bc;
    float* bud = Bu + br * BGP + bc;

    const int wn = tid >> 5, lane = tid & 31;
    const int qr = lane >> 2, qc = lane & 3;
    const int abuf = BM * AS_P, bbuf = BK * BGP;

    float accG[4][4][4], accU[4][4][4];
    #pragma unroll
    for (int m = 0; m < 4; m++)
        #pragma unroll
        for (int n = 0; n < 4; n++)
            #pragma unroll
            for (int j = 0; j < 4; j++) { accG[m][n][j] = 0.f; accU[m][n][j] = 0.f; }

    // prologue: stage 0 -> buf 0
    #pragma unroll
    for (int l = 0; l < 4; l++) cpa16(a_dst[l], a_src[l]);
    #pragma unroll
    for (int l = 0; l < 8; l++) {
        cpa16(bgd + l * 4 * BGP, bgs + (size_t)l * 4 * TWO_I);
        cpa16(bud + l * 4 * BGP, bus + (size_t)l * 4 * TWO_I);
    }
    cpa_commit();

    const int KT = Hn / BK;  // 32
    for (int kt = 0; kt < KT; kt++) {
        const int buf = kt & 1;
        cpa_wait0();       // own stage-kt copies retired
        __syncthreads();   // globalize stage-kt; all warps past compute(kt-1)
        if (kt + 1 < KT) {
            const int aoff = (buf ^ 1) ? abuf : 0;
            const int boff = (buf ^ 1) ? bbuf : 0;
            const size_t ka = (size_t)(kt + 1) * BK;
            #pragma unroll
            for (int l = 0; l < 4; l++) cpa16(a_dst[l] + aoff, a_src[l] + ka);
            #pragma unroll
            for (int l = 0; l < 8; l++) {
                cpa16(bgd + boff + l * 4 * BGP, bgs + ka * TWO_I + (size_t)l * 4 * TWO_I);
                cpa16(bud + boff + l * 4 * BGP, bus + ka * TWO_I + (size_t)l * 4 * TWO_I);
            }
            cpa_commit();
        }

        const float* Ab = As + buf * abuf;
        const float* Bgb = Bg + buf * bbuf;
        const float* Bub = Bu + buf * bbuf;
        #pragma unroll
        for (int ks = 0; ks < BK; ks += 8) {
            unsigned a[4][4];
            #pragma unroll
            for (int m = 0; m < 4; m++) {
                int r0 = m * 16 + qr;
                a[m][0] = __float_as_uint(Ab[r0 * AS_P + ks + qc]);
                a[m][1] = __float_as_uint(Ab[(r0 + 8) * AS_P + ks + qc]);
                a[m][2] = __float_as_uint(Ab[r0 * AS_P + ks + qc + 4]);
                a[m][3] = __float_as_uint(Ab[(r0 + 8) * AS_P + ks + qc + 4]);
            }
            #pragma unroll
            for (int n = 0; n < 4; n++) {
                int c = wn * 32 + n * 8 + qr;
                unsigned bg0 = __float_as_uint(Bgb[(ks + qc) * BGP + c]);
                unsigned bg1 = __float_as_uint(Bgb[(ks + qc + 4) * BGP + c]);
                #pragma unroll
                for (int m = 0; m < 4; m++)
                    mma_tf32(accG[m][n], a[m][0], a[m][1], a[m][2], a[m][3], bg0, bg1);
                unsigned bu0 = __float_as_uint(Bub[(ks + qc) * BGP + c]);
                unsigned bu1 = __float_as_uint(Bub[(ks + qc + 4) * BGP + c]);
                #pragma unroll
                for (int m = 0; m < 4; m++)
                    mma_tf32(accU[m][n], a[m][0], a[m][1], a[m][2], a[m][3], bu0, bu1);
            }
        }
    }

    // epilogue: bias-correct, silu(g)*u -> raw fp32 (slot = e*Tn + row)
    float* arow_base = g_act + (size_t)e * Tn * In;
    #pragma unroll
    for (int m = 0; m < 4; m++) {
        #pragma unroll
        for (int n = 0; n < 4; n++) {
            #pragma unroll
            for (int half_ = 0; half_ < 2; half_++) {
                int r = m * 16 + qr + half_ * 8;
                int grow = row0 + r;
                if (grow < n_e) {
                    int c = colg + wn * 32 + n * 8 + qc * 2;
                    float gv0 = accG[m][n][half_ * 2 + 0] * CF1;
                    float uv0 = accU[m][n][half_ * 2 + 0] * CF1;
                    float gv1 = accG[m][n][half_ * 2 + 1] * CF1;
                    float uv1 = accU[m][n][half_ * 2 + 1] * CF1;
                    float2 o;
                    o.x = gv0 / (1.f + expf(-gv0)) * uv0;
                    o.y = gv1 / (1.f + expf(-gv1)) * uv1;
                    *(float2*)(arow_base + (size_t)grow * In + c) = o;
                }
            }
        }
    }
}

// ---------------- kernel 4: down GEMM (tf32 raw-bit) + fused weighted combine ----
// R12 shape: 128 threads, block 64M x 256N, warp 64M x 64N. Epilogue applies the
// routing weight and red.global.add.v2.f32 into out[token] (L2-resident 4MB).
__global__ __launch_bounds__(128, 2) void k_gemm2(const float* __restrict__ wd,
                                                  const float* __restrict__ shd,
                                                  float* __restrict__ out) {
    const int e = blockIdx.y;
    const int n_e = (e < En) ? g_counts[e] : Tn;
    const int nb = blockIdx.x & 3;
    const int mt = blockIdx.x >> 2;
    const int row0 = mt * BM;
    if (row0 >= n_e) return;
    const float* Bp = (e < En) ? (wd + (size_t)e * In * Hn) : shd;
    const int colb = nb * 256;

    extern __shared__ float smem[];
    float* As = smem;                    // [2][64][AS_P]
    float* Bs = smem + 2 * BM * AS_P;    // [2][32][BSP2]

    const int tid = threadIdx.x;
    const float* arow_base = g_act + (size_t)e * Tn * In;

    const int ar = tid >> 3, ac = (tid & 7) * 4;
    const float* a_src[4];
    float* a_dst[4];
    #pragma unroll
    for (int l = 0; l < 4; l++) {
        int r = l * 16 + ar;
        int ridx = row0 + r; if (ridx > n_e - 1) ridx = n_e - 1;
        a_src[l] = arow_base + (size_t)ridx * In + ac;
        a_dst[l] = As + r * AS_P + ac;
    }
    const int br = tid >> 6, bc = (tid & 63) * 4;
    const float* bss = Bp + (size_t)br * Hn + colb + bc;
    float* bsd = Bs + br * BSP2 + bc;

    const int wn = tid >> 5, lane = tid & 31;
    const int qr = lane >> 2, qc = lane & 3;
    const int abuf = BM * AS_P, bbuf = BK * BSP2;

    float acc[4][8][4];
    #pragma unroll
    for (int m = 0; m < 4; m++)
        #pragma unroll
        for (int n = 0; n < 8; n++)
            #pragma unroll
            for (int j = 0; j < 4; j++) acc[m][n][j] = 0.f;

    #pragma unroll
    for (int l = 0; l < 4; l++) cpa16(a_dst[l], a_src[l]);
    #pragma unroll
    for (int l = 0; l < 16; l++)
        cpa16(bsd + l * 2 * BSP2, bss + (size_t)l * 2 * Hn);
    cpa_commit();

    const int KT = In / BK;  // 16
    for (int kt = 0; kt < KT; kt++) {
        const int buf = kt & 1;
        cpa_wait0();
        __syncthreads();
        if (kt + 1 < KT) {
            const int aoff = (buf ^ 1) ? abuf : 0;
            const int boff = (buf ^ 1) ? bbuf : 0;
            const size_t ka = (size_t)(kt + 1) * BK;
            #pragma unroll
            for (int l = 0; l < 4; l++) cpa16(a_dst[l] + aoff, a_src[l] + ka);
            #pragma unroll
            for (int l = 0; l < 16; l++)
                cpa16(bsd + boff + l * 2 * BSP2, bss + ka * Hn + (size_t)l * 2 * Hn);
            cpa_commit();
        }

        const float* Ab = As + buf * abuf;
        const float* Bb = Bs + buf * bbuf;
        #pragma unroll
        for (int ks = 0; ks < BK; ks += 8) {
            unsigned a[4][4];
            #pragma unroll
            for (int m = 0; m < 4; m++) {
                int r0 = m * 16 + qr;
                a[m][0] = __float_as_uint(Ab[r0 * AS_P + ks + qc]);
                a[m][1] = __float_as_uint(Ab[(r0 + 8) * AS_P + ks + qc]);
                a[m][2] = __float_as_uint(Ab[r0 * AS_P + ks + qc + 4]);
                a[m][3] = __float_as_uint(Ab[(r0 + 8) * AS_P + ks + qc + 4]);
            }
            #pragma unroll
            for (int n = 0; n < 8; n++) {
                int c = wn * 64 + n * 8 + qr;
                unsigned b0 = __float_as_uint(Bb[(ks + qc) * BSP2 + c]);
                unsigned b1 = __float_as_uint(Bb[(ks + qc + 4) * BSP2 + c]);
                #pragma unroll
                for (int m = 0; m < 4; m++)
                    mma_tf32(acc[m][n], a[m][0], a[m][1], a[m][2], a[m][3], b0, b1);
            }
        }
    }

    // epilogue: weighted scatter-accumulate into out[token]
    #pragma unroll
    for (int m = 0; m < 4; m++) {
        #pragma unroll
        for (int half_ = 0; half_ < 2; half_++) {
            int r = m * 16 + qr + half_ * 8;
            int grow = row0 + r;
            if (grow < n_e) {
                int tok;
                float wv;
                if (e < En) {
                    tok = g_tokens[e * Tn + grow];
                    wv  = g_wslot[e * Tn + grow];
                } else {
                    tok = grow;
                    wv  = CF2;
                }
                float* orow = out + (size_t)tok * Hn + colb + wn * 64 + qc * 2;
                #pragma unroll
                for (int n = 0; n < 8; n++) {
                    red_add_v2(orow + n * 8,
                               acc[m][n][half_ * 2 + 0] * wv,
                               acc[m][n][half_ * 2 + 1] * wv);
                }
            }
        }
    }
}

// ---------------- launch ----------------
extern "C" void kernel_launch(void* const* d_in, const int* in_sizes, int n_in,
                              void* d_out, int out_size) {
    const float* x    = (const float*)d_in[0];
    const float* gw   = (const float*)d_in[1];
    const float* eb   = (const float*)d_in[2];
    const float* wgu  = (const float*)d_in[3];
    const float* wd   = (const float*)d_in[4];
    const float* shgu = (const float*)d_in[5];
    const float* shd  = (const float*)d_in[6];
    float* out = (float*)d_out;

    const int smem1 = (2 * BM * AS_P + 4 * BK * BGP) * 4;   // 88064 B
    const int smem2 = (2 * BM * AS_P + 2 * BK * BSP2) * 4;  // 86016 B
    cudaFuncSetAttribute(k_gemm1, cudaFuncAttributeMaxDynamicSharedMemorySize, smem1);
    cudaFuncSetAttribute(k_gemm2, cudaFuncAttributeMaxDynamicSharedMemorySize, smem2);

    void* counts_ptr = nullptr;
    cudaGetSymbolAddress(&counts_ptr, g_counts);

    cudaMemsetAsync(out, 0, (size_t)out_size * sizeof(float));
    cudaMemsetAsync(counts_ptr, 0, En * sizeof(int));
    k_route<<<Tn / 4, 256>>>(x, gw, eb);
    k_gemm1<<<dim3(16 * 4, NV), 128, smem1>>>(x, wgu, shgu);
    k_gemm2<<<dim3(16 * 4, NV), 128, smem2>>>(wd, shd, out);
}